// round 5
// baseline (speedup 1.0000x reference)
#include <cuda_runtime.h>
#include <math.h>

// ---------------------------------------------------------------------------
// StateModelEncoder — round 4: full CSR gather (all 4 edge sets), mega-fused
// state dense chain (layers 2-5 in one kernel), p-form TAG hops, fused head.
// ---------------------------------------------------------------------------

#define NVn 100000
#define NSn 50000
#define EVVmax 1600000
#define ESSmax 800000
#define EHmax  800000
#define EINmax 800000

// ------------------------- scratch (device globals) ------------------------
__device__ __align__(16) float g_xpad[NVn * 8];
__device__ float g_dinv_v[NVn];
__device__ __align__(16) float g_z[NVn * 40];          // [x5|rgcn15|hops15|pad5]
__device__ __align__(16) float g_pv[2][NVn * 8];
__device__ __align__(16) float g_Wz[40 * 64];
__device__ float g_c0[64];
__device__ __align__(16) float g_WzW[4][40 * 64];
__device__ float g_c0W[4][64];
__device__ __align__(16) float g_sx5[NSn * 64];
__device__ __align__(16) float g_pin[NSn * 64];
__device__ __align__(16) float g_pk[3][NSn * 64];      // TAG-state p-form hops
__device__ __align__(16) float g_sx6[NSn * 64];
__device__ __align__(16) float g_accs5[NSn * 64];
__device__ float g_dinv_s[NSn];
__device__ float g_sqd_s[NSn];
__device__ float g_cntf_s[NSn];

// CSR structures (4 graphs)
__device__ int g_deg_vv[NVn]; __device__ int g_off_vv[NVn]; __device__ int g_cur_vv[NVn];
__device__ int g_tmp_vv[NVn]; __device__ int g_part_vv[128];
__device__ int g_csr_vv[EVVmax];                       // src | (etype<<20)
__device__ int g_deg_ss[NSn]; __device__ int g_off_ss[NSn]; __device__ int g_cur_ss[NSn];
__device__ int g_tmp_ss[NSn]; __device__ int g_part_ss[128];
__device__ int g_csr_ss[ESSmax];
__device__ int g_deg_h[NSn];  __device__ int g_off_h[NSn];  __device__ int g_cur_h[NSn];
__device__ int g_tmp_h[NSn];  __device__ int g_part_h[128];
__device__ int g_csr_h[EHmax]; __device__ float g_csrw_h[EHmax];
__device__ int g_deg_in[NSn]; __device__ int g_off_in[NSn]; __device__ int g_cur_in[NSn];
__device__ int g_tmp_in[NSn]; __device__ int g_part_in[128];
__device__ int g_csr_in[EINmax];

// ------------------------------ CSR build ----------------------------------
__global__ void k_count_i(const int* __restrict__ ei, int* __restrict__ deg, int E) {
    int e = blockIdx.x * blockDim.x + threadIdx.x;
    if (e >= E) return;
    atomicAdd(deg + ei[E + e], 1);
}

__global__ void k_scan1(const int* __restrict__ deg, int* __restrict__ incl,
                        int* __restrict__ part, int n) {
    __shared__ int sh[1024];
    int i = blockIdx.x * 1024 + threadIdx.x;
    int v = (i < n) ? deg[i] : 0;
    sh[threadIdx.x] = v;
    __syncthreads();
    for (int o = 1; o < 1024; o <<= 1) {
        int t = (threadIdx.x >= o) ? sh[threadIdx.x - o] : 0;
        __syncthreads();
        sh[threadIdx.x] += t;
        __syncthreads();
    }
    if (i < n) incl[i] = sh[threadIdx.x];
    if (threadIdx.x == 1023) part[blockIdx.x] = sh[1023];
}

__global__ void k_scan2(int* __restrict__ part, int nb) {
    __shared__ int sh[128];
    int v = (threadIdx.x < nb) ? part[threadIdx.x] : 0;
    sh[threadIdx.x] = v;
    __syncthreads();
    for (int o = 1; o < 128; o <<= 1) {
        int t = (threadIdx.x >= o) ? sh[threadIdx.x - o] : 0;
        __syncthreads();
        sh[threadIdx.x] += t;
        __syncthreads();
    }
    if (threadIdx.x < nb) part[threadIdx.x] = sh[threadIdx.x] - v;  // exclusive
}

__global__ void k_scan3(const int* __restrict__ deg, const int* __restrict__ incl,
                        const int* __restrict__ part, int* __restrict__ off,
                        int* __restrict__ cur, int n) {
    int i = blockIdx.x * blockDim.x + threadIdx.x;
    if (i >= n) return;
    int o = incl[i] - deg[i] + part[i >> 10];
    off[i] = o;
    cur[i] = o;
}

__global__ void k_fill_vv(const int* __restrict__ ei, const int* __restrict__ et, int E) {
    int e = blockIdx.x * blockDim.x + threadIdx.x;
    if (e >= E) return;
    int s = ei[e], d = ei[E + e], t = et[e];
    int slot = atomicAdd(g_cur_vv + d, 1);
    g_csr_vv[slot] = s | (t << 20);
}

__global__ void k_fill_ss(const int* __restrict__ ei, int E) {
    int e = blockIdx.x * blockDim.x + threadIdx.x;
    if (e >= E) return;
    int slot = atomicAdd(g_cur_ss + ei[E + e], 1);
    g_csr_ss[slot] = ei[e];
}

__global__ void k_fill_h(const int* __restrict__ ei, const float* __restrict__ ew, int E) {
    int e = blockIdx.x * blockDim.x + threadIdx.x;
    if (e >= E) return;
    int slot = atomicAdd(g_cur_h + ei[E + e], 1);
    g_csr_h[slot] = ei[e];
    g_csrw_h[slot] = ew[e];
}

__global__ void k_fill_in(const int* __restrict__ ei, int E) {
    int e = blockIdx.x * blockDim.x + threadIdx.x;
    if (e >= E) return;
    int slot = atomicAdd(g_cur_in + ei[E + e], 1);
    g_csr_in[slot] = ei[e];
}

__global__ void k_dinv_v() {
    int v = blockIdx.x * blockDim.x + threadIdx.x;
    if (v >= NVn) return;
    int d = g_deg_vv[v];
    g_dinv_v[v] = (d > 0) ? rsqrtf((float)d) : 0.f;
}

__global__ void k_dinv_s() {
    int v = blockIdx.x * blockDim.x + threadIdx.x;
    if (v >= NSn) return;
    int d = g_deg_ss[v];
    g_dinv_s[v] = (d > 0) ? rsqrtf((float)d) : 0.f;
    g_sqd_s[v]  = sqrtf((float)d);
    g_cntf_s[v] = (float)d;
}

// ------------------------------ weight prep --------------------------------
__global__ void k_prep1(const float* __restrict__ W1_rel, const float* __restrict__ W1_root,
                        const float* __restrict__ b1,
                        const float* __restrict__ W12, const float* __restrict__ b12) {
    int t = blockIdx.x * blockDim.x + threadIdx.x;
    if (t < 64) g_c0[t] = b1[t] + b12[t];
    if (t >= 40 * 64) return;
    int i = t >> 6, c = t & 63;
    float w = 0.f;
    if (i < 5)        w = W1_root[i * 64 + c] + W12[i * 64 + c];
    else if (i < 20)  w = W1_rel[(i - 5) * 64 + c];
    else if (i < 35)  w = W12[(i - 15) * 64 + c];
    g_Wz[t] = w;
}

__global__ void k_prep2(const float* __restrict__ W3_rel, const float* __restrict__ W32_l,
                        const float* __restrict__ W4_l,  const float* __restrict__ W42_l) {
    int t = blockIdx.x * blockDim.x + threadIdx.x;
    if (t >= 4 * 41 * 64) return;
    int m = t / (41 * 64);
    int r = t % (41 * 64);
    int i = r >> 6, c = r & 63;
    const float* Wm = (m == 0) ? W3_rel : (m == 1) ? W32_l : (m == 2) ? W4_l : W42_l;
    float acc = 0.f;
    if (i < 40) {
        const float* zr = g_Wz + i * 64;
#pragma unroll 8
        for (int j = 0; j < 64; j++) acc += zr[j] * Wm[j * 64 + c];
        g_WzW[m][i * 64 + c] = acc;
    } else {
#pragma unroll 8
        for (int j = 0; j < 64; j++) acc += g_c0[j] * Wm[j * 64 + c];
        g_c0W[m][c] = acc;
    }
}

// --------------------------- game-graph kernels ----------------------------
__global__ void k_pad(const float* __restrict__ x) {
    int t = blockIdx.x * blockDim.x + threadIdx.x;
    if (t >= NVn * 8) return;
    int v = t >> 3, i = t & 7;
    float xv = (i < 5) ? x[v * 5 + i] : 0.f;
    g_xpad[t] = xv;
    if (i < 5) g_z[(size_t)v * 40 + i] = xv;
}

// RGCN per-rel means + TAG-game hop1, fused. warp/dst, 8-lane subgroup/edge.
__global__ void k_rgcn_hop1(float* __restrict__ p1) {
    int gt = blockIdx.x * blockDim.x + threadIdx.x;
    int w = gt >> 5, lane = gt & 31;
    if (w >= NVn) return;
    int base = g_off_vv[w], deg = g_deg_vv[w];
    int sub = lane >> 3, li = lane & 7;
    float a0 = 0.f, a1 = 0.f, a2 = 0.f, ah = 0.f;
    float c0 = 0.f, c1 = 0.f, c2 = 0.f;
    for (int j = sub; j < deg; j += 4) {
        int pk = g_csr_vv[base + j];
        int s = pk & 0xFFFFF, t = pk >> 20;
        float xv = g_xpad[(size_t)s * 8 + li];
        ah += g_dinv_v[s] * xv;
        if (t == 0)      { a0 += xv; c0 += 1.f; }
        else if (t == 1) { a1 += xv; c1 += 1.f; }
        else             { a2 += xv; c2 += 1.f; }
    }
#pragma unroll
    for (int o = 8; o < 32; o <<= 1) {
        a0 += __shfl_xor_sync(0xffffffffu, a0, o);
        a1 += __shfl_xor_sync(0xffffffffu, a1, o);
        a2 += __shfl_xor_sync(0xffffffffu, a2, o);
        ah += __shfl_xor_sync(0xffffffffu, ah, o);
        c0 += __shfl_xor_sync(0xffffffffu, c0, o);
        c1 += __shfl_xor_sync(0xffffffffu, c1, o);
        c2 += __shfl_xor_sync(0xffffffffu, c2, o);
    }
    if (sub == 0) {
        float dvd = g_dinv_v[w];
        float h1 = dvd * ah;
        if (li < 5) {
            float* zz = g_z + (size_t)w * 40;
            zz[5 + li]  = a0 / fmaxf(c0, 1.f);
            zz[10 + li] = a1 / fmaxf(c1, 1.f);
            zz[15 + li] = a2 / fmaxf(c2, 1.f);
            zz[20 + li] = h1;
        }
        p1[(size_t)w * 8 + li] = dvd * h1;
    }
}

// TAG-game hop k (k=1,2): h = dinv_d * sum(p_prev[src]); write z slice (+p_next).
__global__ void k_hop8_gather(const float* __restrict__ pprev, float* __restrict__ pnext,
                              int k, int write_p) {
    int gt = blockIdx.x * blockDim.x + threadIdx.x;
    int w = gt >> 5, lane = gt & 31;
    if (w >= NVn) return;
    int base = g_off_vv[w], deg = g_deg_vv[w];
    int sub = lane >> 3, li = lane & 7;
    float acc = 0.f;
    for (int j = sub; j < deg; j += 4) {
        int s = g_csr_vv[base + j] & 0xFFFFF;
        acc += pprev[(size_t)s * 8 + li];
    }
#pragma unroll
    for (int o = 8; o < 32; o <<= 1)
        acc += __shfl_xor_sync(0xffffffffu, acc, o);
    if (sub == 0) {
        float dv = g_dinv_v[w];
        float h = dv * acc;
        if (li < 5) g_z[(size_t)w * 40 + 20 + k * 5 + li] = h;
        if (write_p) pnext[(size_t)w * 8 + li] = dv * h;
    }
}

// ------------- mega kernel: ei_h + ei_in gathers, state layers 2-5 ---------
__global__ void __launch_bounds__(256) k_state_mega(
        const float* __restrict__ state_x, const float* __restrict__ W3_root,
        const float* __restrict__ b3, const float* __restrict__ W32_r,
        const float* __restrict__ b32, const float* __restrict__ W4_r,
        const float* __restrict__ b4, const float* __restrict__ W42_r,
        const float* __restrict__ b42) {
    __shared__ float s_aggw[4][40];
    __shared__ float s_aggu[4][40];
    __shared__ float s_aggin[4][40];
    __shared__ float s_wsum[4], s_cnth[4], s_cntin[4];
    __shared__ float s_sx[2][4][64];
    int tid = threadIdx.x;
    int warp = tid >> 5, lane = tid & 31;
    int vbase = blockIdx.x * 4;

    {   // gather phase: warps 0-3 -> ei_h, warps 4-7 -> ei_in (node = warp&3)
        int n = warp & 3;
        int v = vbase + n;
        if (warp < 4) {
            int base = g_off_h[v], deg = g_deg_h[v];
            float aw0 = 0.f, aw1 = 0.f, au0 = 0.f, au1 = 0.f, ws = 0.f, ct = 0.f;
            for (int j0 = 0; j0 < deg; j0 += 32) {
                int idx = j0 + lane;
                int sl = 0; float wl = 0.f;
                if (idx < deg) { sl = g_csr_h[base + idx]; wl = g_csrw_h[base + idx]; ws += wl; ct += 1.f; }
                int m = deg - j0; if (m > 32) m = 32;
                for (int jj = 0; jj < m; jj++) {
                    int s = __shfl_sync(0xffffffffu, sl, jj);
                    float wt = __shfl_sync(0xffffffffu, wl, jj);
                    float z1 = g_z[(size_t)s * 40 + lane];
                    aw0 += wt * z1; au0 += z1;
                    if (lane < 3) {
                        float z2 = g_z[(size_t)s * 40 + 32 + lane];
                        aw1 += wt * z2; au1 += z2;
                    }
                }
            }
            s_aggw[n][lane] = aw0; s_aggu[n][lane] = au0;
            if (lane < 3) { s_aggw[n][32 + lane] = aw1; s_aggu[n][32 + lane] = au1; }
#pragma unroll
            for (int o = 16; o; o >>= 1) {
                ws += __shfl_xor_sync(0xffffffffu, ws, o);
                ct += __shfl_xor_sync(0xffffffffu, ct, o);
            }
            if (lane == 0) { s_wsum[n] = ws; s_cnth[n] = ct; }
        } else {
            int base = g_off_in[v], deg = g_deg_in[v];
            float a0 = 0.f, a1 = 0.f, ct = 0.f;
            for (int j0 = 0; j0 < deg; j0 += 32) {
                int idx = j0 + lane;
                int sl = 0;
                if (idx < deg) { sl = g_csr_in[base + idx]; ct += 1.f; }
                int m = deg - j0; if (m > 32) m = 32;
                for (int jj = 0; jj < m; jj++) {
                    int s = __shfl_sync(0xffffffffu, sl, jj);
                    a0 += g_z[(size_t)s * 40 + lane];
                    if (lane < 3) a1 += g_z[(size_t)s * 40 + 32 + lane];
                }
            }
            s_aggin[n][lane] = a0;
            if (lane < 3) s_aggin[n][32 + lane] = a1;
#pragma unroll
            for (int o = 16; o; o >>= 1) ct += __shfl_xor_sync(0xffffffffu, ct, o);
            if (lane == 0) s_cntin[n] = ct;
        }
    }
    __syncthreads();

    // dense phase: 64 threads per node
    int n = tid >> 6, c = tid & 63;
    int v = vbase + n;

    // L2: graph_conv
    {
        float acc = b3[c] + s_wsum[n] * g_c0W[0][c];
        const float* W = g_WzW[0];
#pragma unroll 7
        for (int i = 0; i < 35; i++) acc += s_aggw[n][i] * W[i * 64 + c];
        const float* xv = state_x + (size_t)v * 5;
#pragma unroll
        for (int j = 0; j < 5; j++) acc += xv[j] * W3_root[j * 64 + c];
        s_sx[0][n][c] = fmaxf(acc, 0.f);
    }
    __syncthreads();
    // L3: conv32 (mean over ei_h)
    {
        float ch = s_cnth[n];
        float inv = 1.f / fmaxf(ch, 1.f);
        const float* W = g_WzW[1];
        float sa = 0.f;
#pragma unroll 7
        for (int i = 0; i < 35; i++) sa += s_aggu[n][i] * W[i * 64 + c];
        float acc = b32[c] + sa * inv + ((ch > 0.f) ? g_c0W[1][c] : 0.f);
#pragma unroll 8
        for (int j = 0; j < 64; j++) acc += s_sx[0][n][j] * W32_r[j * 64 + c];
        s_sx[1][n][c] = fmaxf(acc, 0.f);
    }
    __syncthreads();
    // L4: conv4 (mean over ei_in)
    {
        float ci = s_cntin[n];
        float inv = 1.f / fmaxf(ci, 1.f);
        const float* W = g_WzW[2];
        float sa = 0.f;
#pragma unroll 7
        for (int i = 0; i < 35; i++) sa += s_aggin[n][i] * W[i * 64 + c];
        float acc = b4[c] + sa * inv + ((ci > 0.f) ? g_c0W[2][c] : 0.f);
#pragma unroll 8
        for (int j = 0; j < 64; j++) acc += s_sx[1][n][j] * W4_r[j * 64 + c];
        s_sx[0][n][c] = fmaxf(acc, 0.f);
    }
    __syncthreads();
    // L5: conv42
    {
        float ci = s_cntin[n];
        float inv = 1.f / fmaxf(ci, 1.f);
        const float* W = g_WzW[3];
        float sa = 0.f;
#pragma unroll 7
        for (int i = 0; i < 35; i++) sa += s_aggin[n][i] * W[i * 64 + c];
        float acc = b42[c] + sa * inv + ((ci > 0.f) ? g_c0W[3][c] : 0.f);
#pragma unroll 8
        for (int j = 0; j < 64; j++) acc += s_sx[0][n][j] * W42_r[j * 64 + c];
        float sx5 = fmaxf(acc, 0.f);
        g_sx5[(size_t)v * 64 + c] = sx5;
        g_pin[(size_t)v * 64 + c] = g_dinv_s[v] * sx5;
    }
}

// TAG-state hop, p-form only: p_next = dinv^2 * sum(p_prev[src]).
__global__ void k_hop64p(const float* __restrict__ pprev, float* __restrict__ pnext) {
    int gt = blockIdx.x * blockDim.x + threadIdx.x;
    int w = gt >> 5, lane = gt & 31;
    if (w >= NSn) return;
    int base = g_off_ss[w], deg = g_deg_ss[w];
    float a = 0.f, b = 0.f;
    for (int j = 0; j < deg; j += 32) {
        int idx = j + lane;
        int sl = (idx < deg) ? g_csr_ss[base + idx] : 0;
        int m = deg - j; if (m > 32) m = 32;
        for (int jj = 0; jj < m; jj++) {
            int s = __shfl_sync(0xffffffffu, sl, jj);
            const float* f = pprev + (size_t)s * 64;
            a += f[lane];
            b += f[lane + 32];
        }
    }
    float dv = g_dinv_s[w];
    float dv2 = dv * dv;
    pnext[(size_t)w * 64 + lane] = dv2 * a;
    pnext[(size_t)w * 64 + lane + 32] = dv2 * b;
}

// TAG-state out: relu(b2 + sx5@W2_0 + sqrt(deg) * sum_k p_k@W2_{k+1})
__global__ void k_tag_out(const float* __restrict__ W2, const float* __restrict__ b2) {
    int t = blockIdx.x * blockDim.x + threadIdx.x;
    int v = t >> 6, c = t & 63;
    if (v >= NSn) return;
    float acc = b2[c];
    const float* s0 = g_sx5 + (size_t)v * 64;
#pragma unroll 8
    for (int j = 0; j < 64; j++) acc += s0[j] * W2[j * 64 + c];
    float h = 0.f;
#pragma unroll
    for (int k = 0; k < 3; k++) {
        const float* pk = g_pk[k] + (size_t)v * 64;
        const float* wk = W2 + (size_t)(k + 1) * 4096;
#pragma unroll 8
        for (int j = 0; j < 64; j++) h += pk[j] * wk[j * 64 + c];
    }
    acc += g_sqd_s[v] * h;
    g_sx6[(size_t)v * 64 + c] = fmaxf(acc, 0.f);
}

// conv5 sum gather over ei_ss.
__global__ void k_sum64_gather(const float* __restrict__ feat, float* __restrict__ acc) {
    int gt = blockIdx.x * blockDim.x + threadIdx.x;
    int w = gt >> 5, lane = gt & 31;
    if (w >= NSn) return;
    int base = g_off_ss[w], deg = g_deg_ss[w];
    float a = 0.f, b = 0.f;
    for (int j = 0; j < deg; j += 32) {
        int idx = j + lane;
        int sl = (idx < deg) ? g_csr_ss[base + idx] : 0;
        int m = deg - j; if (m > 32) m = 32;
        for (int jj = 0; jj < m; jj++) {
            int s = __shfl_sync(0xffffffffu, sl, jj);
            const float* f = feat + (size_t)s * 64;
            a += f[lane];
            b += f[lane + 32];
        }
    }
    acc[(size_t)w * 64 + lane] = a;
    acc[(size_t)w * 64 + lane + 32] = b;
}

// conv5 SAGE + linear head, fused.
__global__ void __launch_bounds__(256) k_conv5_final(
        const float* __restrict__ W5_l, const float* __restrict__ W5_r,
        const float* __restrict__ b5, const float* __restrict__ Wl,
        const float* __restrict__ bl, float* __restrict__ out) {
    __shared__ float s7[4][64];
    int tid = threadIdx.x;
    int n = tid >> 6, c = tid & 63;
    int v = blockIdx.x * 4 + n;
    float inv = 1.f / fmaxf(g_cntf_s[v], 1.f);
    const float* av = g_accs5 + (size_t)v * 64;
    float sa = 0.f;
#pragma unroll 8
    for (int j = 0; j < 64; j++) sa += av[j] * W5_l[j * 64 + c];
    float acc = b5[c] + sa * inv;
    const float* xv = g_sx6 + (size_t)v * 64;
#pragma unroll 8
    for (int j = 0; j < 64; j++) acc += xv[j] * W5_r[j * 64 + c];
    s7[n][c] = fmaxf(acc, 0.f);
    __syncthreads();
    if (c < 8) {
        float o = bl[c];
#pragma unroll 8
        for (int j = 0; j < 64; j++) o += s7[n][j] * Wl[j * 8 + c];
        out[(size_t)v * 8 + c] = o;
    }
}

// ------------------------------- launch ------------------------------------

extern "C" void kernel_launch(void* const* d_in, const int* in_sizes, int n_in,
                              void* d_out, int out_size) {
    const float* game_x  = (const float*)d_in[0];
    const float* state_x = (const float*)d_in[1];
    const int*   ei_vv   = (const int*)d_in[2];
    const int*   et_vv   = (const int*)d_in[3];
    const int*   ei_h    = (const int*)d_in[4];
    const float* ew_h    = (const float*)d_in[5];
    const int*   ei_in   = (const int*)d_in[6];
    const int*   ei_ss   = (const int*)d_in[7];
    const float* W1_rel  = (const float*)d_in[8];
    const float* W1_root = (const float*)d_in[9];
    const float* b1      = (const float*)d_in[10];
    const float* W12     = (const float*)d_in[11];
    const float* b12     = (const float*)d_in[12];
    const float* W2      = (const float*)d_in[13];
    const float* b2      = (const float*)d_in[14];
    const float* W3_rel  = (const float*)d_in[15];
    const float* W3_root = (const float*)d_in[16];
    const float* b3      = (const float*)d_in[17];
    const float* W32_l   = (const float*)d_in[18];
    const float* W32_r   = (const float*)d_in[19];
    const float* b32     = (const float*)d_in[20];
    const float* W4_l    = (const float*)d_in[21];
    const float* W4_r    = (const float*)d_in[22];
    const float* b4      = (const float*)d_in[23];
    const float* W42_l   = (const float*)d_in[24];
    const float* W42_r   = (const float*)d_in[25];
    const float* b42     = (const float*)d_in[26];
    const float* W5_l    = (const float*)d_in[27];
    const float* W5_r    = (const float*)d_in[28];
    const float* b5      = (const float*)d_in[29];
    const float* Wl      = (const float*)d_in[30];
    const float* bl      = (const float*)d_in[31];
    float* out = (float*)d_out;

    int Evv = in_sizes[2] / 2;
    int Eh  = in_sizes[4] / 2;
    int Ein = in_sizes[6] / 2;
    int Ess = in_sizes[7] / 2;

    // symbol addresses
    int *pi_deg_vv, *pi_tmp_vv, *pi_part_vv, *pi_off_vv, *pi_cur_vv;
    int *pi_deg_ss, *pi_tmp_ss, *pi_part_ss, *pi_off_ss, *pi_cur_ss;
    int *pi_deg_h,  *pi_tmp_h,  *pi_part_h,  *pi_off_h,  *pi_cur_h;
    int *pi_deg_in, *pi_tmp_in, *pi_part_in, *pi_off_in, *pi_cur_in;
    float *p_pv, *p_pin, *p_pk, *p_sx6, *p_accs5;
    cudaGetSymbolAddress((void**)&pi_deg_vv, g_deg_vv);
    cudaGetSymbolAddress((void**)&pi_tmp_vv, g_tmp_vv);
    cudaGetSymbolAddress((void**)&pi_part_vv,g_part_vv);
    cudaGetSymbolAddress((void**)&pi_off_vv, g_off_vv);
    cudaGetSymbolAddress((void**)&pi_cur_vv, g_cur_vv);
    cudaGetSymbolAddress((void**)&pi_deg_ss, g_deg_ss);
    cudaGetSymbolAddress((void**)&pi_tmp_ss, g_tmp_ss);
    cudaGetSymbolAddress((void**)&pi_part_ss,g_part_ss);
    cudaGetSymbolAddress((void**)&pi_off_ss, g_off_ss);
    cudaGetSymbolAddress((void**)&pi_cur_ss, g_cur_ss);
    cudaGetSymbolAddress((void**)&pi_deg_h,  g_deg_h);
    cudaGetSymbolAddress((void**)&pi_tmp_h,  g_tmp_h);
    cudaGetSymbolAddress((void**)&pi_part_h, g_part_h);
    cudaGetSymbolAddress((void**)&pi_off_h,  g_off_h);
    cudaGetSymbolAddress((void**)&pi_cur_h,  g_cur_h);
    cudaGetSymbolAddress((void**)&pi_deg_in, g_deg_in);
    cudaGetSymbolAddress((void**)&pi_tmp_in, g_tmp_in);
    cudaGetSymbolAddress((void**)&pi_part_in,g_part_in);
    cudaGetSymbolAddress((void**)&pi_off_in, g_off_in);
    cudaGetSymbolAddress((void**)&pi_cur_in, g_cur_in);
    cudaGetSymbolAddress((void**)&p_pv,    g_pv);
    cudaGetSymbolAddress((void**)&p_pin,   g_pin);
    cudaGetSymbolAddress((void**)&p_pk,    g_pk);
    cudaGetSymbolAddress((void**)&p_sx6,   g_sx6);
    cudaGetSymbolAddress((void**)&p_accs5, g_accs5);

    float* p_pv0 = p_pv;
    float* p_pv1 = p_pv + (size_t)NVn * 8;
    float* p_pk0 = p_pk;
    float* p_pk1 = p_pk + (size_t)NSn * 64;
    float* p_pk2 = p_pk1 + (size_t)NSn * 64;

    const int T = 256;
    auto nb = [](long n, int t) { return (int)((n + t - 1) / t); };
    int nbv_warp = nb((long)NVn * 32, T);
    int nbs_warp = nb((long)NSn * 32, T);

    // 0) zero degree arrays
    cudaMemsetAsync(pi_deg_vv, 0, (size_t)NVn * 4, 0);
    cudaMemsetAsync(pi_deg_ss, 0, (size_t)NSn * 4, 0);
    cudaMemsetAsync(pi_deg_h,  0, (size_t)NSn * 4, 0);
    cudaMemsetAsync(pi_deg_in, 0, (size_t)NSn * 4, 0);

    // 1) weight prep
    k_prep1<<<nb(40 * 64, T), T>>>(W1_rel, W1_root, b1, W12, b12);
    k_prep2<<<nb(4 * 41 * 64, T), T>>>(W3_rel, W32_l, W4_l, W42_l);

    // 2) CSR builds
    k_count_i<<<nb(Evv, T), T>>>(ei_vv, pi_deg_vv, Evv);
    k_scan1<<<nb(NVn, 1024), 1024>>>(pi_deg_vv, pi_tmp_vv, pi_part_vv, NVn);
    k_scan2<<<1, 128>>>(pi_part_vv, nb(NVn, 1024));
    k_scan3<<<nb(NVn, T), T>>>(pi_deg_vv, pi_tmp_vv, pi_part_vv, pi_off_vv, pi_cur_vv, NVn);
    k_fill_vv<<<nb(Evv, T), T>>>(ei_vv, et_vv, Evv);
    k_dinv_v<<<nb(NVn, T), T>>>();

    k_count_i<<<nb(Ess, T), T>>>(ei_ss, pi_deg_ss, Ess);
    k_scan1<<<nb(NSn, 1024), 1024>>>(pi_deg_ss, pi_tmp_ss, pi_part_ss, NSn);
    k_scan2<<<1, 128>>>(pi_part_ss, nb(NSn, 1024));
    k_scan3<<<nb(NSn, T), T>>>(pi_deg_ss, pi_tmp_ss, pi_part_ss, pi_off_ss, pi_cur_ss, NSn);
    k_fill_ss<<<nb(Ess, T), T>>>(ei_ss, Ess);
    k_dinv_s<<<nb(NSn, T), T>>>();

    k_count_i<<<nb(Eh, T), T>>>(ei_h, pi_deg_h, Eh);
    k_scan1<<<nb(NSn, 1024), 1024>>>(pi_deg_h, pi_tmp_h, pi_part_h, NSn);
    k_scan2<<<1, 128>>>(pi_part_h, nb(NSn, 1024));
    k_scan3<<<nb(NSn, T), T>>>(pi_deg_h, pi_tmp_h, pi_part_h, pi_off_h, pi_cur_h, NSn);
    k_fill_h<<<nb(Eh, T), T>>>(ei_h, ew_h, Eh);

    k_count_i<<<nb(Ein, T), T>>>(ei_in, pi_deg_in, Ein);
    k_scan1<<<nb(NSn, 1024), 1024>>>(pi_deg_in, pi_tmp_in, pi_part_in, NSn);
    k_scan2<<<1, 128>>>(pi_part_in, nb(NSn, 1024));
    k_scan3<<<nb(NSn, T), T>>>(pi_deg_in, pi_tmp_in, pi_part_in, pi_off_in, pi_cur_in, NSn);
    k_fill_in<<<nb(Ein, T), T>>>(ei_in, Ein);

    // 3) game graph -> z (35 dims used)
    k_pad<<<nb((long)NVn * 8, T), T>>>(game_x);
    k_rgcn_hop1<<<nbv_warp, T>>>(p_pv0);
    k_hop8_gather<<<nbv_warp, T>>>(p_pv0, p_pv1, 1, 1);
    k_hop8_gather<<<nbv_warp, T>>>(p_pv1, p_pv0, 2, 0);

    // 4) mega: ei_h + ei_in gathers, state layers 2-5 -> sx5, pin
    k_state_mega<<<NSn / 4, 256>>>(state_x, W3_root, b3, W32_r, b32, W4_r, b4, W42_r, b42);

    // 5) TAG-state hops (p-form) + output
    k_hop64p<<<nbs_warp, T>>>(p_pin, p_pk0);
    k_hop64p<<<nbs_warp, T>>>(p_pk0, p_pk1);
    k_hop64p<<<nbs_warp, T>>>(p_pk1, p_pk2);
    k_tag_out<<<nb((long)NSn * 64, T), T>>>(W2, b2);

    // 6) conv5 + head
    k_sum64_gather<<<nbs_warp, T>>>(p_sx6, p_accs5);
    k_conv5_final<<<NSn / 4, 256>>>(W5_l, W5_r, b5, Wl, bl, out);
}